// round 16
// baseline (speedup 1.0000x reference)
#include <cuda_runtime.h>
#include <cuda_fp16.h>
#include <math.h>
#include <stdint.h>

// Problem constants
#define B_SZ 4
#define T_SZ 2048
#define C_SZ 1024
#define NH   16
#define HD   64
#define MTOK (B_SZ * T_SZ)
#define QKV_STRIDE (3 * C_SZ)

// Scratch (device globals — no allocations allowed)
__device__ __half g_qkvh[(size_t)MTOK * QKV_STRIDE]; // 48 MB (fp16, RoPE in-place)
__device__ __half g_xh[(size_t)MTOK * C_SZ];         // 16 MB  x as fp16
__device__ __half g_yh[(size_t)MTOK * C_SZ];         // 16 MB  attention out fp16
__device__ __half g_wah[(size_t)(3 * C_SZ) * C_SZ];  // 6 MB   w_attn^T fp16 [N][K]
__device__ __half g_wph[(size_t)C_SZ * C_SZ];        // 2 MB   w_proj^T fp16 [N][K]

// ---------------------------------------------------------------------------
// Helpers
// ---------------------------------------------------------------------------
__device__ __forceinline__ void mma_f16(float c[4],
    uint32_t a0, uint32_t a1, uint32_t a2, uint32_t a3,
    uint32_t b0, uint32_t b1)
{
    asm volatile(
        "mma.sync.aligned.m16n8k16.row.col.f32.f16.f16.f32 "
        "{%0,%1,%2,%3}, {%4,%5,%6,%7}, {%8,%9}, {%0,%1,%2,%3};"
        : "+f"(c[0]), "+f"(c[1]), "+f"(c[2]), "+f"(c[3])
        : "r"(a0), "r"(a1), "r"(a2), "r"(a3), "r"(b0), "r"(b1));
}

__device__ __forceinline__ void ldsm4(uint32_t r[4], uint32_t saddr) {
    asm volatile("ldmatrix.sync.aligned.m8n8.x4.shared.b16 {%0,%1,%2,%3}, [%4];"
                 : "=r"(r[0]), "=r"(r[1]), "=r"(r[2]), "=r"(r[3]) : "r"(saddr));
}

__device__ __forceinline__ void ldsm4t(uint32_t r[4], uint32_t saddr) {
    asm volatile("ldmatrix.sync.aligned.m8n8.x4.trans.shared.b16 {%0,%1,%2,%3}, [%4];"
                 : "=r"(r[0]), "=r"(r[1]), "=r"(r[2]), "=r"(r[3]) : "r"(saddr));
}

__device__ __forceinline__ uint32_t smem_u32(const void* p) {
    return (uint32_t)__cvta_generic_to_shared(p);
}

__device__ __forceinline__ void cp16s(uint32_t saddr, const void* g) {
    asm volatile("cp.async.cg.shared.global [%0], [%1], 16;" :: "r"(saddr), "l"(g));
}
#define CP_COMMIT() asm volatile("cp.async.commit_group;")

// ---------------------------------------------------------------------------
// Pre-pass: fp32 -> fp16 elementwise
// ---------------------------------------------------------------------------
__global__ __launch_bounds__(256) void cvt_half_kernel(
    const float* __restrict__ src, __half* __restrict__ dst)
{
    int i = (blockIdx.x * 256 + threadIdx.x) * 4;
    float4 v = *(const float4*)(src + i);
    *(half2*)(dst + i)     = __floats2half2_rn(v.x, v.y);
    *(half2*)(dst + i + 2) = __floats2half2_rn(v.z, v.w);
}

// ---------------------------------------------------------------------------
// Pre-pass: transpose+convert weights: src[K][N] fp32 -> dst[N][K] fp16
// ---------------------------------------------------------------------------
__global__ __launch_bounds__(256) void transpose_half_kernel(
    const float* __restrict__ src, __half* __restrict__ dst, int K, int N)
{
    __shared__ __half t[32][34];
    int n0 = blockIdx.x * 32, k0 = blockIdx.y * 32;
    int c = threadIdx.x & 31, r = threadIdx.x >> 5;  // 32 x 8
    #pragma unroll
    for (int i = 0; i < 4; i++)
        t[r + 8 * i][c] = __float2half_rn(src[(size_t)(k0 + r + 8 * i) * N + n0 + c]);
    __syncthreads();
    #pragma unroll
    for (int i = 0; i < 4; i++)
        dst[(size_t)(n0 + r + 8 * i) * K + k0 + c] = t[c][r + 8 * i];
}

// ---------------------------------------------------------------------------
// FP16 GEMM (mma.sync m16n8k16): C[M,N] = Ah[M,K] @ Bh[N,K]^T + bias
//   Tile 128x256, K-chunk 64 halfs, 256 threads = 8 warps (2m x 4n),
//   warp tile 64x64 (same per-warp shape as the 159us kernel).
//   3-stage cp.async ring, ONE __syncthreads per chunk (canonical order):
//     wait_group -> __syncthreads -> fill freed stage -> compute.
//   1 CTA/SM (166KB smem), 8 warps/SM. MMA order per element unchanged.
// ---------------------------------------------------------------------------
#define PAD_G 72
#define G_TILE_N 256
#define G_STAGE_H ((128 + G_TILE_N) * PAD_G)     // halfs per stage = 27648
#define G_NSTAGE 3
#define G_SMEM_BYTES (G_NSTAGE * G_STAGE_H * 2)  // 165888

template <typename OutT>
__global__ __launch_bounds__(256) void gemm_f16_kernel(
    const __half* __restrict__ Ah, const __half* __restrict__ Bh,
    const float* __restrict__ bias, OutT* __restrict__ C,
    int M, int N, int K)
{
    extern __shared__ __half gsm[];
    const uint32_t gsm_sh = smem_u32(gsm);

    const int tid  = threadIdx.x;
    const int wid  = tid >> 5;
    const int lane = tid & 31;
    const int g    = lane >> 2;
    const int tig  = lane & 3;
    const int wm   = (wid & 1) * 64;     // 2-way m split
    const int wn   = (wid >> 1) * 64;    // 4-way n split over 256

    const int bm = blockIdx.y * 128;
    const int bn = blockIdx.x * G_TILE_N;

    const int arow = (lane & 7) + ((lane >> 3) & 1) * 8;
    const int acol = ((lane >> 4) & 1) * 8;
    const int brow = (lane & 7) + ((lane >> 4) & 1) * 8;
    const int bcol = ((lane >> 3) & 1) * 8;
    const uint32_t a_off = 2u * ((wm + arow) * PAD_G + acol);
    const uint32_t b_off = 2u * (128 * PAD_G + (wn + brow) * PAD_G + bcol);

    float acc[4][8][4] = {};

    // fill stage s with K-chunk c (A: 128x64 halfs, B: 256x64 halfs)
    auto fill = [&](int s, int c) {
        __half* As_ = gsm + s * G_STAGE_H;
        __half* Bs_ = As_ + 128 * PAD_G;
        #pragma unroll
        for (int p = 0; p < 4; p++) {            // A: 1024 16B-chunks
            int id = tid + 256 * p;
            int r = id >> 3, u = id & 7;
            cp16s(smem_u32(&As_[r * PAD_G + u * 8]),
                  Ah + (size_t)(bm + r) * K + c * 64 + u * 8);
        }
        #pragma unroll
        for (int p = 0; p < 8; p++) {            // B: 2048 16B-chunks
            int id = tid + 256 * p;
            int r = id >> 3, u = id & 7;
            cp16s(smem_u32(&Bs_[r * PAD_G + u * 8]),
                  Bh + (size_t)(bn + r) * K + c * 64 + u * 8);
        }
        CP_COMMIT();
    };

    const int NC = K >> 6;       // 16 for K=1024
    fill(0, 0);
    fill(1, 1);

    for (int kt = 0; kt < NC; kt++) {
        if (kt < NC - 1) asm volatile("cp.async.wait_group 1;");
        else             asm volatile("cp.async.wait_group 0;");
        __syncthreads();
        if (kt + 2 < NC) fill((kt + 2) % 3, kt + 2);

        const uint32_t st = gsm_sh + 2u * ((kt % 3) * G_STAGE_H);
        const uint32_t aB = st + a_off;
        const uint32_t bB = st + b_off;

        #pragma unroll
        for (int kk = 0; kk < 64; kk += 16) {
            uint32_t af[4][4];
            #pragma unroll
            for (int mi = 0; mi < 4; mi++)
                ldsm4(af[mi], aB + 2u * (16 * mi * PAD_G + kk));
            #pragma unroll
            for (int p = 0; p < 4; p++) {
                uint32_t bq[4];
                ldsm4(bq, bB + 2u * (16 * p * PAD_G + kk));
                #pragma unroll
                for (int mi = 0; mi < 4; mi++) {
                    mma_f16(acc[mi][2 * p],     af[mi][0], af[mi][1], af[mi][2], af[mi][3], bq[0], bq[1]);
                    mma_f16(acc[mi][2 * p + 1], af[mi][0], af[mi][1], af[mi][2], af[mi][3], bq[2], bq[3]);
                }
            }
        }
    }

    // epilogue: bias + store (fp32 or fp16)
    #pragma unroll
    for (int ni = 0; ni < 8; ni++) {
        int col = bn + wn + 8 * ni + 2 * tig;
        float bx = bias[col], by = bias[col + 1];
        #pragma unroll
        for (int mi = 0; mi < 4; mi++) {
            int row0 = bm + wm + 16 * mi + g;
            if constexpr (sizeof(OutT) == 4) {
                float2 o0 = {acc[mi][ni][0] + bx, acc[mi][ni][1] + by};
                float2 o1 = {acc[mi][ni][2] + bx, acc[mi][ni][3] + by};
                *(float2*)((float*)C + (size_t)row0 * N + col) = o0;
                *(float2*)((float*)C + (size_t)(row0 + 8) * N + col) = o1;
            } else {
                *(half2*)((__half*)C + (size_t)row0 * N + col) =
                    __floats2half2_rn(acc[mi][ni][0] + bx, acc[mi][ni][1] + by);
                *(half2*)((__half*)C + (size_t)(row0 + 8) * N + col) =
                    __floats2half2_rn(acc[mi][ni][2] + bx, acc[mi][ni][3] + by);
            }
        }
    }
}

// ---------------------------------------------------------------------------
// RoPE on fp16 qkv (fp32 math inside; powf -> exp2f constant multiply)
// ---------------------------------------------------------------------------
__global__ __launch_bounds__(256) void rope_half_kernel(__half* __restrict__ qkv)
{
    int idx = blockIdx.x * blockDim.x + threadIdx.x;
    int pair = idx & 31;
    int h    = (idx >> 5) & (NH - 1);
    int tok  = idx >> 9;
    int t    = tok & (T_SZ - 1);

    // invf = 10000^(-pair/32) = 2^(-pair * log2(10000)/32)
    const float LOG2_10000_DIV32 = 0.41524101186297083f;
    float invf = exp2f(-(float)pair * LOG2_10000_DIV32);
    float ang = (float)t * invf;
    float s, c;
    sincosf(ang, &s, &c);

    size_t base = (size_t)tok * QKV_STRIDE + h * HD;
    __half* q = qkv + base;
    __half* k = qkv + base + C_SZ;

    float q1 = __half2float(q[pair]), q2 = __half2float(q[pair + 32]);
    q[pair]      = __float2half_rn(q1 * c - q2 * s);
    q[pair + 32] = __float2half_rn(q2 * c + q1 * s);
    float k1 = __half2float(k[pair]), k2 = __half2float(k[pair + 32]);
    k[pair]      = __float2half_rn(k1 * c - k2 * s);
    k[pair + 32] = __float2half_rn(k2 * c + k1 * s);
}

// ---------------------------------------------------------------------------
// FP16 flash attention (causal) — unchanged from round 15.
// ---------------------------------------------------------------------------
#define PAD_H 72
#define KV_TILE_H (64 * PAD_H)
#define FQH 0
#define FKH (128 * PAD_H)
#define FVH (FKH + 2 * KV_TILE_H)
#define FPH (FVH + 2 * KV_TILE_H)
#define FA_SMEM_H (FPH + 128 * PAD_H)
#define FA_SMEM_BYTES (FA_SMEM_H * 2)      // 73728

__global__ __launch_bounds__(128) void flash_f16_kernel(
    const __half* __restrict__ qkv, __half* __restrict__ yh)
{
    extern __shared__ __half fsm[];
    __half* Ps = fsm + FPH;
    const uint32_t fsm_sh = smem_u32(fsm);

    const int qt = blockIdx.x;
    const int h  = blockIdx.y;
    const int b  = blockIdx.z;
    const int tid  = threadIdx.x;
    const int w    = tid >> 5;
    const int lane = tid & 31;
    const int g    = lane >> 2;
    const int tig  = lane & 3;

    const int arow = (lane & 7) + ((lane >> 3) & 1) * 8;
    const int acol = ((lane >> 4) & 1) * 8;
    const int brow = (lane & 7) + ((lane >> 4) & 1) * 8;   // non-trans (K)
    const int bcol = ((lane >> 3) & 1) * 8;
    const int vrow = (lane & 7) + ((lane >> 3) & 1) * 8;   // trans (V)
    const int vcol = ((lane >> 4) & 1) * 8;

    const uint32_t aq_base = fsm_sh + 2u * (FQH + (32 * w + arow) * PAD_H + acol);
    const uint32_t ap_base = fsm_sh + 2u * (FPH + (32 * w + arow) * PAD_H + acol);
    const uint32_t bk_base = fsm_sh + 2u * (FKH + brow * PAD_H + bcol);
    const uint32_t bv_base = fsm_sh + 2u * (FVH + vrow * PAD_H + vcol);

    const __half* qbase = qkv + (size_t)b * T_SZ * QKV_STRIDE + h * HD;
    const __half* kbase = qbase + C_SZ;
    const __half* vbase = qbase + 2 * C_SZ;

    auto fill_kv = [&](int s, int kt) {
        __half* Kd = fsm + FKH + s * KV_TILE_H;
        __half* Vd = fsm + FVH + s * KV_TILE_H;
        #pragma unroll
        for (int p = 0; p < 4; p++) {
            int id = tid + 128 * p;
            int r = id >> 3, u = id & 7;
            cp16s(smem_u32(&Kd[r * PAD_H + u * 8]),
                  kbase + (size_t)(kt * 64 + r) * QKV_STRIDE + u * 8);
            cp16s(smem_u32(&Vd[r * PAD_H + u * 8]),
                  vbase + (size_t)(kt * 64 + r) * QKV_STRIDE + u * 8);
        }
        CP_COMMIT();
    };

    {
        __half* Qd = fsm + FQH;
        #pragma unroll
        for (int p = 0; p < 8; p++) {
            int id = tid + 128 * p;
            int r = id >> 3, u = id & 7;
            cp16s(smem_u32(&Qd[r * PAD_H + u * 8]),
                  qbase + (size_t)(qt * 128 + r) * QKV_STRIDE + u * 8);
        }
    }
    fill_kv(0, 0);

    float m[2][2], l[2][2];
    #pragma unroll
    for (int mi = 0; mi < 2; mi++) {
        m[mi][0] = -INFINITY; m[mi][1] = -INFINITY;
        l[mi][0] = 0.0f;      l[mi][1] = 0.0f;
    }
    float o[2][8][4] = {};

    const int wrow_lo = qt * 128 + 32 * w;
    const int ktmax = 2 * qt + 1;

    for (int kt = 0; kt <= ktmax; kt++) {
        const int s = kt & 1;
        if (kt < ktmax) {
            fill_kv(s ^ 1, kt + 1);
            asm volatile("cp.async.wait_group 1;");
        } else {
            asm volatile("cp.async.wait_group 0;");
        }
        __syncthreads();

        const bool active = (kt * 64 <= wrow_lo + 31);
        if (active) {
            const uint32_t bkS = bk_base + 2u * (s * KV_TILE_H);
            const uint32_t bvS = bv_base + 2u * (s * KV_TILE_H);

            float sv[2][8][4] = {};
            #pragma unroll
            for (int kk = 0; kk < 64; kk += 16) {
                uint32_t af[2][4];
                ldsm4(af[0], aq_base + 2u * kk);
                ldsm4(af[1], aq_base + 2u * (16 * PAD_H + kk));
                #pragma unroll
                for (int p = 0; p < 4; p++) {
                    uint32_t bq[4];
                    ldsm4(bq, bkS + 2u * (16 * p * PAD_H + kk));
                    #pragma unroll
                    for (int mi = 0; mi < 2; mi++) {
                        mma_f16(sv[mi][2 * p],     af[mi][0], af[mi][1], af[mi][2], af[mi][3], bq[0], bq[1]);
                        mma_f16(sv[mi][2 * p + 1], af[mi][0], af[mi][1], af[mi][2], af[mi][3], bq[2], bq[3]);
                    }
                }
            }

            #pragma unroll
            for (int mi = 0; mi < 2; mi++)
                #pragma unroll
                for (int ni = 0; ni < 8; ni++) {
                    sv[mi][ni][0] *= 0.125f; sv[mi][ni][1] *= 0.125f;
                    sv[mi][ni][2] *= 0.125f; sv[mi][ni][3] *= 0.125f;
                }
            if (kt * 64 + 63 > wrow_lo) {
                #pragma unroll
                for (int mi = 0; mi < 2; mi++) {
                    int row0 = wrow_lo + 16 * mi + g;
                    int row1 = row0 + 8;
                    #pragma unroll
                    for (int ni = 0; ni < 8; ni++) {
                        int col = kt * 64 + 8 * ni + 2 * tig;
                        if (col     > row0) sv[mi][ni][0] = -INFINITY;
                        if (col + 1 > row0) sv[mi][ni][1] = -INFINITY;
                        if (col     > row1) sv[mi][ni][2] = -INFINITY;
                        if (col + 1 > row1) sv[mi][ni][3] = -INFINITY;
                    }
                }
            }

            #pragma unroll
            for (int mi = 0; mi < 2; mi++) {
                float mx0 = sv[mi][0][0], mx1 = sv[mi][0][2];
                #pragma unroll
                for (int ni = 0; ni < 8; ni++) {
                    mx0 = fmaxf(mx0, fmaxf(sv[mi][ni][0], sv[mi][ni][1]));
                    mx1 = fmaxf(mx1, fmaxf(sv[mi][ni][2], sv[mi][ni][3]));
                }
                mx0 = fmaxf(mx0, __shfl_xor_sync(0xffffffffu, mx0, 1));
                mx0 = fmaxf(mx0, __shfl_xor_sync(0xffffffffu, mx0, 2));
                mx1 = fmaxf(mx1, __shfl_xor_sync(0xffffffffu, mx1, 1));
                mx1 = fmaxf(mx1, __shfl_xor_sync(0xffffffffu, mx1, 2));

                float mn0 = fmaxf(m[mi][0], mx0), mn1 = fmaxf(m[mi][1], mx1);
                float al0 = __expf(m[mi][0] - mn0), al1 = __expf(m[mi][1] - mn1);

                __half* pw0 = Ps + (32 * w + 16 * mi + g) * PAD_H + 2 * tig;
                __half* pw1 = pw0 + 8 * PAD_H;
                float r0 = 0.0f, r1 = 0.0f;
                #pragma unroll
                for (int ni = 0; ni < 8; ni++) {
                    float p0 = __expf(sv[mi][ni][0] - mn0);
                    float p1 = __expf(sv[mi][ni][1] - mn0);
                    float p2 = __expf(sv[mi][ni][2] - mn1);
                    float p3 = __expf(sv[mi][ni][3] - mn1);
                    r0 += p0 + p1;
                    r1 += p2 + p3;
                    *(half2*)(pw0 + 8 * ni) = __floats2half2_rn(p0, p1);
                    *(half2*)(pw1 + 8 * ni) = __floats2half2_rn(p2, p3);
                }
                r0 += __shfl_xor_sync(0xffffffffu, r0, 1);
                r0 += __shfl_xor_sync(0xffffffffu, r0, 2);
                r1 += __shfl_xor_sync(0xffffffffu, r1, 1);
                r1 += __shfl_xor_sync(0xffffffffu, r1, 2);

                l[mi][0] = l[mi][0] * al0 + r0;
                l[mi][1] = l[mi][1] * al1 + r1;
                m[mi][0] = mn0;
                m[mi][1] = mn1;

                #pragma unroll
                for (int ni = 0; ni < 8; ni++) {
                    o[mi][ni][0] *= al0; o[mi][ni][1] *= al0;
                    o[mi][ni][2] *= al1; o[mi][ni][3] *= al1;
                }
            }

            __syncwarp();

            #pragma unroll
            for (int kk = 0; kk < 64; kk += 16) {
                uint32_t af[2][4];
                ldsm4(af[0], ap_base + 2u * kk);
                ldsm4(af[1], ap_base + 2u * (16 * PAD_H + kk));
                #pragma unroll
                for (int p = 0; p < 4; p++) {
                    uint32_t bq[4];
                    ldsm4t(bq, bvS + 2u * (kk * PAD_H + 16 * p));
                    #pragma unroll
                    for (int mi = 0; mi < 2; mi++) {
                        mma_f16(o[mi][2 * p],     af[mi][0], af[mi][1], af[mi][2], af[mi][3], bq[0], bq[1]);
                        mma_f16(o[mi][2 * p + 1], af[mi][0], af[mi][1], af[mi][2], af[mi][3], bq[2], bq[3]);
                    }
                }
            }
        }
        __syncthreads();
    }

    #pragma unroll
    for (int mi = 0; mi < 2; mi++) {
        float inv0 = 1.0f / l[mi][0], inv1 = 1.0f / l[mi][1];
        int row0 = qt * 128 + 32 * w + 16 * mi + g;
        int row1 = row0 + 8;
        #pragma unroll
        for (int ni = 0; ni < 8; ni++) {
            int col = h * HD + 8 * ni + 2 * tig;
            *(half2*)(yh + ((size_t)b * T_SZ + row0) * C_SZ + col) =
                __floats2half2_rn(o[mi][ni][0] * inv0, o[mi][ni][1] * inv0);
            *(half2*)(yh + ((size_t)b * T_SZ + row1) * C_SZ + col) =
                __floats2half2_rn(o[mi][ni][2] * inv1, o[mi][ni][3] * inv1);
        }
    }
}

// ---------------------------------------------------------------------------
// Launch
// ---------------------------------------------------------------------------
extern "C" void kernel_launch(void* const* d_in, const int* in_sizes, int n_in,
                              void* d_out, int out_size)
{
    const float* x      = (const float*)d_in[0];
    const float* w_attn = (const float*)d_in[1];
    const float* b_attn = (const float*)d_in[2];
    const float* w_proj = (const float*)d_in[3];
    const float* b_proj = (const float*)d_in[4];
    float* out = (float*)d_out;

    __half *qkvh = nullptr, *xh = nullptr, *yh = nullptr, *wah = nullptr, *wph = nullptr;
    cudaGetSymbolAddress((void**)&qkvh, g_qkvh);
    cudaGetSymbolAddress((void**)&xh, g_xh);
    cudaGetSymbolAddress((void**)&yh, g_yh);
    cudaGetSymbolAddress((void**)&wah, g_wah);
    cudaGetSymbolAddress((void**)&wph, g_wph);

    cudaFuncSetAttribute(gemm_f16_kernel<__half>,
                         cudaFuncAttributeMaxDynamicSharedMemorySize, G_SMEM_BYTES);
    cudaFuncSetAttribute(gemm_f16_kernel<float>,
                         cudaFuncAttributeMaxDynamicSharedMemorySize, G_SMEM_BYTES);
    cudaFuncSetAttribute(flash_f16_kernel,
                         cudaFuncAttributeMaxDynamicSharedMemorySize, FA_SMEM_BYTES);

    // 0) pre-pass
    cvt_half_kernel<<<(MTOK * C_SZ) / 1024, 256>>>(x, xh);
    {
        dim3 g1(3 * C_SZ / 32, C_SZ / 32);
        transpose_half_kernel<<<g1, 256>>>(w_attn, wah, C_SZ, 3 * C_SZ);
        dim3 g2(C_SZ / 32, C_SZ / 32);
        transpose_half_kernel<<<g2, 256>>>(w_proj, wph, C_SZ, C_SZ);
    }

    // 1) qkv = x @ w_attn + b_attn  -> fp16
    {
        dim3 grid(3 * C_SZ / G_TILE_N, MTOK / 128);
        gemm_f16_kernel<__half><<<grid, 256, G_SMEM_BYTES>>>(xh, wah, b_attn, qkvh,
                                                             MTOK, 3 * C_SZ, C_SZ);
    }
    // 2) RoPE (fp16 in-place)
    {
        int total = MTOK * NH * 32;
        rope_half_kernel<<<total / 256, 256>>>(qkvh);
    }
    // 3) flash attention -> y fp16
    {
        dim3 grid(T_SZ / 128, NH, B_SZ);
        flash_f16_kernel<<<grid, 128, FA_SMEM_BYTES>>>(qkvh, yh);
    }
    // 4) out = y @ w_proj + b_proj  -> fp32
    {
        dim3 grid(C_SZ / G_TILE_N, MTOK / 128);
        gemm_f16_kernel<float><<<grid, 256, G_SMEM_BYTES>>>(yh, wph, b_proj, out,
                                                            MTOK, C_SZ, C_SZ);
    }
}

// round 17
// speedup vs baseline: 1.0905x; 1.0905x over previous
#include <cuda_runtime.h>
#include <cuda_fp16.h>
#include <math.h>
#include <stdint.h>

// Problem constants
#define B_SZ 4
#define T_SZ 2048
#define C_SZ 1024
#define NH   16
#define HD   64
#define MTOK (B_SZ * T_SZ)
#define QKV_STRIDE (3 * C_SZ)

// Scratch (device globals — no allocations allowed)
__device__ __half g_qkvh[(size_t)MTOK * QKV_STRIDE]; // 48 MB (fp16, RoPE fused)
__device__ __half g_xh[(size_t)MTOK * C_SZ];         // 16 MB  x as fp16
__device__ __half g_yh[(size_t)MTOK * C_SZ];         // 16 MB  attention out fp16
__device__ __half g_wah[(size_t)(3 * C_SZ) * C_SZ];  // 6 MB   w_attn^T fp16 [N][K]
__device__ __half g_wph[(size_t)C_SZ * C_SZ];        // 2 MB   w_proj^T fp16 [N][K]
__device__ float2 g_rope[(size_t)T_SZ * 32];         // 512 KB (cos,sin) per (t,d)

// ---------------------------------------------------------------------------
// Helpers
// ---------------------------------------------------------------------------
__device__ __forceinline__ void mma_f16(float c[4],
    uint32_t a0, uint32_t a1, uint32_t a2, uint32_t a3,
    uint32_t b0, uint32_t b1)
{
    asm volatile(
        "mma.sync.aligned.m16n8k16.row.col.f32.f16.f16.f32 "
        "{%0,%1,%2,%3}, {%4,%5,%6,%7}, {%8,%9}, {%0,%1,%2,%3};"
        : "+f"(c[0]), "+f"(c[1]), "+f"(c[2]), "+f"(c[3])
        : "r"(a0), "r"(a1), "r"(a2), "r"(a3), "r"(b0), "r"(b1));
}

__device__ __forceinline__ void ldsm4(uint32_t r[4], uint32_t saddr) {
    asm volatile("ldmatrix.sync.aligned.m8n8.x4.shared.b16 {%0,%1,%2,%3}, [%4];"
                 : "=r"(r[0]), "=r"(r[1]), "=r"(r[2]), "=r"(r[3]) : "r"(saddr));
}

__device__ __forceinline__ void ldsm4t(uint32_t r[4], uint32_t saddr) {
    asm volatile("ldmatrix.sync.aligned.m8n8.x4.trans.shared.b16 {%0,%1,%2,%3}, [%4];"
                 : "=r"(r[0]), "=r"(r[1]), "=r"(r[2]), "=r"(r[3]) : "r"(saddr));
}

__device__ __forceinline__ uint32_t smem_u32(const void* p) {
    return (uint32_t)__cvta_generic_to_shared(p);
}

__device__ __forceinline__ void cp16s(uint32_t saddr, const void* g) {
    asm volatile("cp.async.cg.shared.global [%0], [%1], 16;" :: "r"(saddr), "l"(g));
}
#define CP_COMMIT() asm volatile("cp.async.commit_group;")

// ---------------------------------------------------------------------------
// Pre-pass: rope table  (cos,sin) for (t, d), d = rotation pair 0..31
// ---------------------------------------------------------------------------
__global__ __launch_bounds__(256) void rope_table_kernel()
{
    int idx = blockIdx.x * 256 + threadIdx.x;     // T_SZ*32 total
    int t = idx >> 5, d = idx & 31;
    const float LOG2_10000_DIV32 = 0.41524101186297083f;
    float invf = exp2f(-(float)d * LOG2_10000_DIV32);
    float s, c;
    sincosf((float)t * invf, &s, &c);
    g_rope[idx] = make_float2(c, s);
}

// ---------------------------------------------------------------------------
// Pre-pass: fp32 -> fp16 elementwise
// ---------------------------------------------------------------------------
__global__ __launch_bounds__(256) void cvt_half_kernel(
    const float* __restrict__ src, __half* __restrict__ dst)
{
    int i = (blockIdx.x * 256 + threadIdx.x) * 4;
    float4 v = *(const float4*)(src + i);
    *(half2*)(dst + i)     = __floats2half2_rn(v.x, v.y);
    *(half2*)(dst + i + 2) = __floats2half2_rn(v.z, v.w);
}

// ---------------------------------------------------------------------------
// Pre-pass: transpose+convert weights: src[K][N] fp32 -> dst[N][K] fp16
// ---------------------------------------------------------------------------
__global__ __launch_bounds__(256) void transpose_half_kernel(
    const float* __restrict__ src, __half* __restrict__ dst, int K, int N)
{
    __shared__ __half t[32][34];
    int n0 = blockIdx.x * 32, k0 = blockIdx.y * 32;
    int c = threadIdx.x & 31, r = threadIdx.x >> 5;  // 32 x 8
    #pragma unroll
    for (int i = 0; i < 4; i++)
        t[r + 8 * i][c] = __float2half_rn(src[(size_t)(k0 + r + 8 * i) * N + n0 + c]);
    __syncthreads();
    #pragma unroll
    for (int i = 0; i < 4; i++)
        dst[(size_t)(n0 + r + 8 * i) * K + k0 + c] = t[c][r + 8 * i];
}

// ---------------------------------------------------------------------------
// FP16 GEMM (mma.sync m16n8k16): C[M,N] = Ah[M,K] @ Bh[N,K]^T + bias
//   Round-15 config: tile 128x128, K-chunk 64, 128 threads = 4 warps,
//   warp tile 64x64, 3-stage one-sync pipeline, 2 CTAs/SM.
//   ROPE template flag: fuse RoPE rotation into the fp16 epilogue (QKV GEMM).
//   Each warp's 64-col tile == one head; pair (d, d+32) lives in the same
//   thread as acc[mi][ni] / acc[mi][ni+4]. Rotation in fp32, then fp16 store.
// ---------------------------------------------------------------------------
#define PAD_G 72
#define G_STAGE_H (2 * 128 * PAD_G)          // halfs per stage = 18432
#define G_NSTAGE 3
#define G_SMEM_BYTES (G_NSTAGE * G_STAGE_H * 2)   // 110592

template <typename OutT, bool ROPE>
__global__ __launch_bounds__(128) void gemm_f16_kernel(
    const __half* __restrict__ Ah, const __half* __restrict__ Bh,
    const float* __restrict__ bias, OutT* __restrict__ C,
    int M, int N, int K)
{
    extern __shared__ __half gsm[];
    const uint32_t gsm_sh = smem_u32(gsm);

    const int tid  = threadIdx.x;
    const int wid  = tid >> 5;
    const int lane = tid & 31;
    const int g    = lane >> 2;
    const int tig  = lane & 3;
    const int wm   = (wid & 1) * 64;
    const int wn   = (wid >> 1) * 64;

    const int bm = blockIdx.y * 128;
    const int bn = blockIdx.x * 128;

    const int arow = (lane & 7) + ((lane >> 3) & 1) * 8;
    const int acol = ((lane >> 4) & 1) * 8;
    const int brow = (lane & 7) + ((lane >> 4) & 1) * 8;
    const int bcol = ((lane >> 3) & 1) * 8;
    const uint32_t a_off = 2u * ((wm + arow) * PAD_G + acol);
    const uint32_t b_off = 2u * (128 * PAD_G + (wn + brow) * PAD_G + bcol);

    float acc[4][8][4] = {};

    auto fill = [&](int s, int c) {
        __half* As_ = gsm + s * G_STAGE_H;
        __half* Bs_ = As_ + 128 * PAD_G;
        #pragma unroll
        for (int p = 0; p < 8; p++) {
            int id = tid + 128 * p;
            int r = id >> 3, u = id & 7;
            cp16s(smem_u32(&As_[r * PAD_G + u * 8]),
                  Ah + (size_t)(bm + r) * K + c * 64 + u * 8);
            cp16s(smem_u32(&Bs_[r * PAD_G + u * 8]),
                  Bh + (size_t)(bn + r) * K + c * 64 + u * 8);
        }
        CP_COMMIT();
    };

    const int NC = K >> 6;       // 16 for K=1024
    fill(0, 0);
    fill(1, 1);

    for (int kt = 0; kt < NC; kt++) {
        if (kt < NC - 1) asm volatile("cp.async.wait_group 1;");
        else             asm volatile("cp.async.wait_group 0;");
        __syncthreads();
        if (kt + 2 < NC) fill((kt + 2) % 3, kt + 2);

        const uint32_t st = gsm_sh + 2u * ((kt % 3) * G_STAGE_H);
        const uint32_t aB = st + a_off;
        const uint32_t bB = st + b_off;

        #pragma unroll
        for (int kk = 0; kk < 64; kk += 16) {
            uint32_t af[4][4];
            #pragma unroll
            for (int mi = 0; mi < 4; mi++)
                ldsm4(af[mi], aB + 2u * (16 * mi * PAD_G + kk));
            #pragma unroll
            for (int p = 0; p < 4; p++) {
                uint32_t bq[4];
                ldsm4(bq, bB + 2u * (16 * p * PAD_G + kk));
                #pragma unroll
                for (int mi = 0; mi < 4; mi++) {
                    mma_f16(acc[mi][2 * p],     af[mi][0], af[mi][1], af[mi][2], af[mi][3], bq[0], bq[1]);
                    mma_f16(acc[mi][2 * p + 1], af[mi][0], af[mi][1], af[mi][2], af[mi][3], bq[2], bq[3]);
                }
            }
        }
    }

    // add bias
    #pragma unroll
    for (int ni = 0; ni < 8; ni++) {
        int col = bn + wn + 8 * ni + 2 * tig;
        float bx = bias[col], by = bias[col + 1];
        #pragma unroll
        for (int mi = 0; mi < 4; mi++) {
            acc[mi][ni][0] += bx; acc[mi][ni][1] += by;
            acc[mi][ni][2] += bx; acc[mi][ni][3] += by;
        }
    }

    // fused RoPE (QKV GEMM only): rotate q/k regions. Whole warp is in one
    // region (64-col head-aligned tile). Pair d<->d+32 is ni<->ni+4.
    if constexpr (ROPE) {
        if (bn + wn < 2 * C_SZ) {
            #pragma unroll
            for (int mi = 0; mi < 4; mi++) {
                int r0 = bm + wm + 16 * mi + g;
                int t0 = r0 & (T_SZ - 1);
                int t1 = (r0 + 8) & (T_SZ - 1);
                #pragma unroll
                for (int ni = 0; ni < 4; ni++) {
                    int d = 8 * ni + 2 * tig;    // 0..30
                    float2 c00 = g_rope[t0 * 32 + d];
                    float2 c01 = g_rope[t0 * 32 + d + 1];
                    float2 c10 = g_rope[t1 * 32 + d];
                    float2 c11 = g_rope[t1 * 32 + d + 1];
                    float lo, hi;
                    lo = acc[mi][ni][0]; hi = acc[mi][ni + 4][0];
                    acc[mi][ni][0] = lo * c00.x - hi * c00.y;
                    acc[mi][ni + 4][0] = hi * c00.x + lo * c00.y;
                    lo = acc[mi][ni][1]; hi = acc[mi][ni + 4][1];
                    acc[mi][ni][1] = lo * c01.x - hi * c01.y;
                    acc[mi][ni + 4][1] = hi * c01.x + lo * c01.y;
                    lo = acc[mi][ni][2]; hi = acc[mi][ni + 4][2];
                    acc[mi][ni][2] = lo * c10.x - hi * c10.y;
                    acc[mi][ni + 4][2] = hi * c10.x + lo * c10.y;
                    lo = acc[mi][ni][3]; hi = acc[mi][ni + 4][3];
                    acc[mi][ni][3] = lo * c11.x - hi * c11.y;
                    acc[mi][ni + 4][3] = hi * c11.x + lo * c11.y;
                }
            }
        }
    }

    // store
    #pragma unroll
    for (int ni = 0; ni < 8; ni++) {
        int col = bn + wn + 8 * ni + 2 * tig;
        #pragma unroll
        for (int mi = 0; mi < 4; mi++) {
            int row0 = bm + wm + 16 * mi + g;
            if constexpr (sizeof(OutT) == 4) {
                float2 o0 = {acc[mi][ni][0], acc[mi][ni][1]};
                float2 o1 = {acc[mi][ni][2], acc[mi][ni][3]};
                *(float2*)((float*)C + (size_t)row0 * N + col) = o0;
                *(float2*)((float*)C + (size_t)(row0 + 8) * N + col) = o1;
            } else {
                *(half2*)((__half*)C + (size_t)row0 * N + col) =
                    __floats2half2_rn(acc[mi][ni][0], acc[mi][ni][1]);
                *(half2*)((__half*)C + (size_t)(row0 + 8) * N + col) =
                    __floats2half2_rn(acc[mi][ni][2], acc[mi][ni][3]);
            }
        }
    }
}

// ---------------------------------------------------------------------------
// FP16 flash attention (causal) — round-15 body; qt reversed for tail packing.
// ---------------------------------------------------------------------------
#define PAD_H 72
#define KV_TILE_H (64 * PAD_H)
#define FQH 0
#define FKH (128 * PAD_H)
#define FVH (FKH + 2 * KV_TILE_H)
#define FPH (FVH + 2 * KV_TILE_H)
#define FA_SMEM_H (FPH + 128 * PAD_H)
#define FA_SMEM_BYTES (FA_SMEM_H * 2)      // 73728

__global__ __launch_bounds__(128) void flash_f16_kernel(
    const __half* __restrict__ qkv, __half* __restrict__ yh)
{
    extern __shared__ __half fsm[];
    __half* Ps = fsm + FPH;
    const uint32_t fsm_sh = smem_u32(fsm);

    const int qt = (int)gridDim.x - 1 - (int)blockIdx.x;  // long blocks first
    const int h  = blockIdx.y;
    const int b  = blockIdx.z;
    const int tid  = threadIdx.x;
    const int w    = tid >> 5;
    const int lane = tid & 31;
    const int g    = lane >> 2;
    const int tig  = lane & 3;

    const int arow = (lane & 7) + ((lane >> 3) & 1) * 8;
    const int acol = ((lane >> 4) & 1) * 8;
    const int brow = (lane & 7) + ((lane >> 4) & 1) * 8;   // non-trans (K)
    const int bcol = ((lane >> 3) & 1) * 8;
    const int vrow = (lane & 7) + ((lane >> 3) & 1) * 8;   // trans (V)
    const int vcol = ((lane >> 4) & 1) * 8;

    const uint32_t aq_base = fsm_sh + 2u * (FQH + (32 * w + arow) * PAD_H + acol);
    const uint32_t ap_base = fsm_sh + 2u * (FPH + (32 * w + arow) * PAD_H + acol);
    const uint32_t bk_base = fsm_sh + 2u * (FKH + brow * PAD_H + bcol);
    const uint32_t bv_base = fsm_sh + 2u * (FVH + vrow * PAD_H + vcol);

    const __half* qbase = qkv + (size_t)b * T_SZ * QKV_STRIDE + h * HD;
    const __half* kbase = qbase + C_SZ;
    const __half* vbase = qbase + 2 * C_SZ;

    auto fill_kv = [&](int s, int kt) {
        __half* Kd = fsm + FKH + s * KV_TILE_H;
        __half* Vd = fsm + FVH + s * KV_TILE_H;
        #pragma unroll
        for (int p = 0; p < 4; p++) {
            int id = tid + 128 * p;
            int r = id >> 3, u = id & 7;
            cp16s(smem_u32(&Kd[r * PAD_H + u * 8]),
                  kbase + (size_t)(kt * 64 + r) * QKV_STRIDE + u * 8);
            cp16s(smem_u32(&Vd[r * PAD_H + u * 8]),
                  vbase + (size_t)(kt * 64 + r) * QKV_STRIDE + u * 8);
        }
        CP_COMMIT();
    };

    {
        __half* Qd = fsm + FQH;
        #pragma unroll
        for (int p = 0; p < 8; p++) {
            int id = tid + 128 * p;
            int r = id >> 3, u = id & 7;
            cp16s(smem_u32(&Qd[r * PAD_H + u * 8]),
                  qbase + (size_t)(qt * 128 + r) * QKV_STRIDE + u * 8);
        }
    }
    fill_kv(0, 0);

    float m[2][2], l[2][2];
    #pragma unroll
    for (int mi = 0; mi < 2; mi++) {
        m[mi][0] = -INFINITY; m[mi][1] = -INFINITY;
        l[mi][0] = 0.0f;      l[mi][1] = 0.0f;
    }
    float o[2][8][4] = {};

    const int wrow_lo = qt * 128 + 32 * w;
    const int ktmax = 2 * qt + 1;

    for (int kt = 0; kt <= ktmax; kt++) {
        const int s = kt & 1;
        if (kt < ktmax) {
            fill_kv(s ^ 1, kt + 1);
            asm volatile("cp.async.wait_group 1;");
        } else {
            asm volatile("cp.async.wait_group 0;");
        }
        __syncthreads();

        const bool active = (kt * 64 <= wrow_lo + 31);
        if (active) {
            const uint32_t bkS = bk_base + 2u * (s * KV_TILE_H);
            const uint32_t bvS = bv_base + 2u * (s * KV_TILE_H);

            float sv[2][8][4] = {};
            #pragma unroll
            for (int kk = 0; kk < 64; kk += 16) {
                uint32_t af[2][4];
                ldsm4(af[0], aq_base + 2u * kk);
                ldsm4(af[1], aq_base + 2u * (16 * PAD_H + kk));
                #pragma unroll
                for (int p = 0; p < 4; p++) {
                    uint32_t bq[4];
                    ldsm4(bq, bkS + 2u * (16 * p * PAD_H + kk));
                    #pragma unroll
                    for (int mi = 0; mi < 2; mi++) {
                        mma_f16(sv[mi][2 * p],     af[mi][0], af[mi][1], af[mi][2], af[mi][3], bq[0], bq[1]);
                        mma_f16(sv[mi][2 * p + 1], af[mi][0], af[mi][1], af[mi][2], af[mi][3], bq[2], bq[3]);
                    }
                }
            }

            #pragma unroll
            for (int mi = 0; mi < 2; mi++)
                #pragma unroll
                for (int ni = 0; ni < 8; ni++) {
                    sv[mi][ni][0] *= 0.125f; sv[mi][ni][1] *= 0.125f;
                    sv[mi][ni][2] *= 0.125f; sv[mi][ni][3] *= 0.125f;
                }
            if (kt * 64 + 63 > wrow_lo) {
                #pragma unroll
                for (int mi = 0; mi < 2; mi++) {
                    int row0 = wrow_lo + 16 * mi + g;
                    int row1 = row0 + 8;
                    #pragma unroll
                    for (int ni = 0; ni < 8; ni++) {
                        int col = kt * 64 + 8 * ni + 2 * tig;
                        if (col     > row0) sv[mi][ni][0] = -INFINITY;
                        if (col + 1 > row0) sv[mi][ni][1] = -INFINITY;
                        if (col     > row1) sv[mi][ni][2] = -INFINITY;
                        if (col + 1 > row1) sv[mi][ni][3] = -INFINITY;
                    }
                }
            }

            #pragma unroll
            for (int mi = 0; mi < 2; mi++) {
                float mx0 = sv[mi][0][0], mx1 = sv[mi][0][2];
                #pragma unroll
                for (int ni = 0; ni < 8; ni++) {
                    mx0 = fmaxf(mx0, fmaxf(sv[mi][ni][0], sv[mi][ni][1]));
                    mx1 = fmaxf(mx1, fmaxf(sv[mi][ni][2], sv[mi][ni][3]));
                }
                mx0 = fmaxf(mx0, __shfl_xor_sync(0xffffffffu, mx0, 1));
                mx0 = fmaxf(mx0, __shfl_xor_sync(0xffffffffu, mx0, 2));
                mx1 = fmaxf(mx1, __shfl_xor_sync(0xffffffffu, mx1, 1));
                mx1 = fmaxf(mx1, __shfl_xor_sync(0xffffffffu, mx1, 2));

                float mn0 = fmaxf(m[mi][0], mx0), mn1 = fmaxf(m[mi][1], mx1);
                float al0 = __expf(m[mi][0] - mn0), al1 = __expf(m[mi][1] - mn1);

                __half* pw0 = Ps + (32 * w + 16 * mi + g) * PAD_H + 2 * tig;
                __half* pw1 = pw0 + 8 * PAD_H;
                float r0 = 0.0f, r1 = 0.0f;
                #pragma unroll
                for (int ni = 0; ni < 8; ni++) {
                    float p0 = __expf(sv[mi][ni][0] - mn0);
                    float p1 = __expf(sv[mi][ni][1] - mn0);
                    float p2 = __expf(sv[mi][ni][2] - mn1);
                    float p3 = __expf(sv[mi][ni][3] - mn1);
                    r0 += p0 + p1;
                    r1 += p2 + p3;
                    *(half2*)(pw0 + 8 * ni) = __floats2half2_rn(p0, p1);
                    *(half2*)(pw1 + 8 * ni) = __floats2half2_rn(p2, p3);
                }
                r0 += __shfl_xor_sync(0xffffffffu, r0, 1);
                r0 += __shfl_xor_sync(0xffffffffu, r0, 2);
                r1 += __shfl_xor_sync(0xffffffffu, r1, 1);
                r1 += __shfl_xor_sync(0xffffffffu, r1, 2);

                l[mi][0] = l[mi][0] * al0 + r0;
                l[mi][1] = l[mi][1] * al1 + r1;
                m[mi][0] = mn0;
                m[mi][1] = mn1;

                #pragma unroll
                for (int ni = 0; ni < 8; ni++) {
                    o[mi][ni][0] *= al0; o[mi][ni][1] *= al0;
                    o[mi][ni][2] *= al1; o[mi][ni][3] *= al1;
                }
            }

            __syncwarp();

            #pragma unroll
            for (int kk = 0; kk < 64; kk += 16) {
                uint32_t af[2][4];
                ldsm4(af[0], ap_base + 2u * kk);
                ldsm4(af[1], ap_base + 2u * (16 * PAD_H + kk));
                #pragma unroll
                for (int p = 0; p < 4; p++) {
                    uint32_t bq[4];
                    ldsm4t(bq, bvS + 2u * (kk * PAD_H + 16 * p));
                    #pragma unroll
                    for (int mi = 0; mi < 2; mi++) {
                        mma_f16(o[mi][2 * p],     af[mi][0], af[mi][1], af[mi][2], af[mi][3], bq[0], bq[1]);
                        mma_f16(o[mi][2 * p + 1], af[mi][0], af[mi][1], af[mi][2], af[mi][3], bq[2], bq[3]);
                    }
                }
            }
        }
        __syncthreads();
    }

    #pragma unroll
    for (int mi = 0; mi < 2; mi++) {
        float inv0 = 1.0f / l[mi][0], inv1 = 1.0f / l[mi][1];
        int row0 = qt * 128 + 32 * w + 16 * mi + g;
        int row1 = row0 + 8;
        #pragma unroll
        for (int ni = 0; ni < 8; ni++) {
            int col = h * HD + 8 * ni + 2 * tig;
            *(half2*)(yh + ((size_t)b * T_SZ + row0) * C_SZ + col) =
                __floats2half2_rn(o[mi][ni][0] * inv0, o[mi][ni][1] * inv0);
            *(half2*)(yh + ((size_t)b * T_SZ + row1) * C_SZ + col) =
                __floats2half2_rn(o[mi][ni][2] * inv1, o[mi][ni][3] * inv1);
        }
    }
}

// ---------------------------------------------------------------------------
// Launch
// ---------------------------------------------------------------------------
extern "C" void kernel_launch(void* const* d_in, const int* in_sizes, int n_in,
                              void* d_out, int out_size)
{
    const float* x      = (const float*)d_in[0];
    const float* w_attn = (const float*)d_in[1];
    const float* b_attn = (const float*)d_in[2];
    const float* w_proj = (const float*)d_in[3];
    const float* b_proj = (const float*)d_in[4];
    float* out = (float*)d_out;

    __half *qkvh = nullptr, *xh = nullptr, *yh = nullptr, *wah = nullptr, *wph = nullptr;
    cudaGetSymbolAddress((void**)&qkvh, g_qkvh);
    cudaGetSymbolAddress((void**)&xh, g_xh);
    cudaGetSymbolAddress((void**)&yh, g_yh);
    cudaGetSymbolAddress((void**)&wah, g_wah);
    cudaGetSymbolAddress((void**)&wph, g_wph);

    cudaFuncSetAttribute((const void*)gemm_f16_kernel<__half, true>,
                         cudaFuncAttributeMaxDynamicSharedMemorySize, G_SMEM_BYTES);
    cudaFuncSetAttribute((const void*)gemm_f16_kernel<float, false>,
                         cudaFuncAttributeMaxDynamicSharedMemorySize, G_SMEM_BYTES);
    cudaFuncSetAttribute(flash_f16_kernel,
                         cudaFuncAttributeMaxDynamicSharedMemorySize, FA_SMEM_BYTES);

    // 0) pre-pass: rope table, fp16 conversions, weight transposes
    rope_table_kernel<<<(T_SZ * 32) / 256, 256>>>();
    cvt_half_kernel<<<(MTOK * C_SZ) / 1024, 256>>>(x, xh);
    {
        dim3 g1(3 * C_SZ / 32, C_SZ / 32);
        transpose_half_kernel<<<g1, 256>>>(w_attn, wah, C_SZ, 3 * C_SZ);
        dim3 g2(C_SZ / 32, C_SZ / 32);
        transpose_half_kernel<<<g2, 256>>>(w_proj, wph, C_SZ, C_SZ);
    }

    // 1) qkv = RoPE(x @ w_attn + b_attn)  -> fp16 (RoPE fused in epilogue)
    {
        dim3 grid(3 * C_SZ / 128, MTOK / 128);
        gemm_f16_kernel<__half, true><<<grid, 128, G_SMEM_BYTES>>>(
            xh, wah, b_attn, qkvh, MTOK, 3 * C_SZ, C_SZ);
    }
    // 2) flash attention -> y fp16
    {
        dim3 grid(T_SZ / 128, NH, B_SZ);
        flash_f16_kernel<<<grid, 128, FA_SMEM_BYTES>>>(qkvh, yh);
    }
    // 3) out = y @ w_proj + b_proj  -> fp32
    {
        dim3 grid(C_SZ / 128, MTOK / 128);
        gemm_f16_kernel<float, false><<<grid, 128, G_SMEM_BYTES>>>(
            yh, wph, b_proj, out, MTOK, C_SZ, C_SZ);
    }
}